// round 1
// baseline (speedup 1.0000x reference)
#include <cuda_runtime.h>

#define NBATCH 4
#define BLKT 256

// Transposed weights: [k][o] layout, k = h*40+m, o stride 1 (coalesced).
// Sizes: 1600*128 + 2560*128 + 2560*128 = 860160 floats (3.44 MB, static scratch).
__device__ float g_wT[860160];

__device__ __forceinline__ unsigned long long ffma2(unsigned long long a,
                                                    unsigned long long b,
                                                    unsigned long long c) {
    unsigned long long d;
    asm("fma.rn.f32x2 %0, %1, %2, %3;" : "=l"(d) : "l"(a), "l"(b), "l"(c));
    return d;
}
__device__ __forceinline__ unsigned long long pack2(float lo, float hi) {
    unsigned long long r;
    asm("mov.b64 %0, {%1, %2};" : "=l"(r) : "f"(lo), "f"(hi));
    return r;
}
__device__ __forceinline__ void unpack2(unsigned long long v, float& lo, float& hi) {
    asm("mov.b64 {%0, %1}, %2;" : "=f"(lo), "=f"(hi) : "l"(v));
}

__global__ void transpose_w_kernel(const float* __restrict__ w, int K, int dstOff) {
    int idx = blockIdx.x * blockDim.x + threadIdx.x;
    if (idx < K * 128) {
        int o = idx & 127;
        int k = idx >> 7;
        g_wT[dstOff + idx] = w[o * K + k];
    }
}

// One layer: out[nb][o][d] = relu( sum_h prev[nb][h][d] * (sum_m w[o,h,m]*x[nb][m][d]) + b[o] )
// Channels o<64 -> nextBuf (prev for next layer); o>=64 -> res[nb] += wl * sum_d(out).
// PJ = number of f32x2 pairs per thread (4 -> 8 d's, 2 -> 4 d's).
template<int H, int PJ, bool STORE>
__device__ __forceinline__ void run_layer(
    const float* __restrict__ wT,
    float bv, float wlv,
    const float* __restrict__ xS,
    const float* __restrict__ prev, int prevStride,
    float* __restrict__ nextBuf,
    float* res, int o, int d0)
{
    unsigned long long acc[NBATCH][PJ];
    #pragma unroll
    for (int nb = 0; nb < NBATCH; nb++)
        #pragma unroll
        for (int p = 0; p < PJ; p++) acc[nb][p] = 0ull;

    for (int h = 0; h < H; h++) {
        unsigned long long s[NBATCH][PJ];
        #pragma unroll
        for (int nb = 0; nb < NBATCH; nb++)
            #pragma unroll
            for (int p = 0; p < PJ; p++) s[nb][p] = 0ull;

        const float* wp = wT + h * 40 * 128 + o;
        #pragma unroll 8
        for (int m = 0; m < 40; m++) {
            float wv = __ldg(wp + m * 128);           // coalesced, L2-resident
            unsigned long long w2 = pack2(wv, wv);
            #pragma unroll
            for (int nb = 0; nb < NBATCH; nb++) {
                const float* xp = xS + nb * 640 + m * 16 + d0;
                #pragma unroll
                for (int q = 0; q < PJ / 2; q++) {
                    // broadcast LDS.128 (all lanes same address -> conflict-free)
                    ulonglong2 xv = *reinterpret_cast<const ulonglong2*>(xp + q * 4);
                    s[nb][2 * q]     = ffma2(w2, xv.x, s[nb][2 * q]);
                    s[nb][2 * q + 1] = ffma2(w2, xv.y, s[nb][2 * q + 1]);
                }
            }
        }
        #pragma unroll
        for (int nb = 0; nb < NBATCH; nb++) {
            const float* pp = prev + nb * prevStride + h * 16 + d0;
            #pragma unroll
            for (int q = 0; q < PJ / 2; q++) {
                ulonglong2 pv = *reinterpret_cast<const ulonglong2*>(pp + q * 4);
                acc[nb][2 * q]     = ffma2(pv.x, s[nb][2 * q],     acc[nb][2 * q]);
                acc[nb][2 * q + 1] = ffma2(pv.y, s[nb][2 * q + 1], acc[nb][2 * q + 1]);
            }
        }
    }

    // epilogue: bias + relu, split into prev half / direct half
    #pragma unroll
    for (int nb = 0; nb < NBATCH; nb++) {
        float sumd = 0.f;
        #pragma unroll
        for (int p = 0; p < PJ; p++) {
            float lo, hi;
            unpack2(acc[nb][p], lo, hi);
            lo = fmaxf(lo + bv, 0.f);
            hi = fmaxf(hi + bv, 0.f);
            if (STORE && o < 64) {
                nextBuf[nb * 1024 + o * 16 + d0 + 2 * p]     = lo;
                nextBuf[nb * 1024 + o * 16 + d0 + 2 * p + 1] = hi;
            }
            sumd += lo + hi;
        }
        res[nb] += wlv * sumd;   // wlv == 0 for o < 64
    }
}

__global__ __launch_bounds__(BLKT, 2) void cin_main(
    const float* __restrict__ x,
    const float* __restrict__ b0,
    const float* __restrict__ b1,
    const float* __restrict__ b2,
    const float* __restrict__ wl,
    float* __restrict__ out)
{
    __shared__ __align__(16) float xS[NBATCH * 640];    // x tiles [nb][m=40][d=16]
    __shared__ __align__(16) float pA[NBATCH * 1024];   // prev [nb][h=64][d=16]
    __shared__ __align__(16) float pB[NBATCH * 1024];
    __shared__ float red[8][NBATCH];

    int tid = threadIdx.x;
    int bb = blockIdx.x * NBATCH;

    for (int i = tid; i < NBATCH * 640; i += BLKT)
        xS[i] = x[bb * 640 + i];
    __syncthreads();

    float res[NBATCH] = {0.f, 0.f, 0.f, 0.f};

    int o  = tid & 127;
    int d0 = (tid >> 7) * 8;        // 2 d-halves of 8
    float wlv0 = (o >= 64) ? wl[o - 64]      : 0.f;
    float wlv1 = (o >= 64) ? wl[64 + o - 64] : 0.f;

    // Layer 0: H=40, prev = x itself
    run_layer<40, 4, true >(g_wT,          b0[o], wlv0, xS, xS, 640,  pA, res, o, d0);
    __syncthreads();
    // Layer 1: H=64
    run_layer<64, 4, true >(g_wT + 204800, b1[o], wlv1, xS, pA, 1024, pB, res, o, d0);
    __syncthreads();
    // Layer 2: prev-half is dead (only direct feeds output) -> all 256 threads
    // cover channels 64..127 x 4 d-groups (halves layer-2 FLOPs).
    {
        int o2  = 64 + (tid & 63);
        int d02 = (tid >> 6) * 4;   // 4 d-groups of 4
        float wlv2 = wl[128 + (tid & 63)];
        run_layer<64, 2, false>(g_wT + 532480, b2[o2], wlv2, xS, pB, 1024, nullptr,
                                res, o2, d02);
    }

    // deterministic block reduction (fixed order; no float atomics)
    int lane = tid & 31, wid = tid >> 5;
    #pragma unroll
    for (int nb = 0; nb < NBATCH; nb++) {
        float v = res[nb];
        #pragma unroll
        for (int off = 16; off > 0; off >>= 1)
            v += __shfl_xor_sync(0xffffffffu, v, off);
        if (lane == 0) red[wid][nb] = v;
    }
    __syncthreads();
    if (tid < NBATCH) {
        float t = 0.f;
        #pragma unroll
        for (int w = 0; w < 8; w++) t += red[w][tid];
        out[bb + tid] = t;
    }
}

extern "C" void kernel_launch(void* const* d_in, const int* in_sizes, int n_in,
                              void* d_out, int out_size) {
    const float* x  = (const float*)d_in[0];
    const float* w0 = (const float*)d_in[1];
    const float* b0 = (const float*)d_in[2];
    const float* w1 = (const float*)d_in[3];
    const float* b1 = (const float*)d_in[4];
    const float* w2 = (const float*)d_in[5];
    const float* b2 = (const float*)d_in[6];
    const float* wl = (const float*)d_in[7];
    float* out = (float*)d_out;

    transpose_w_kernel<<<(1600 * 128 + 255) / 256, 256>>>(w0, 1600, 0);
    transpose_w_kernel<<<(2560 * 128 + 255) / 256, 256>>>(w1, 2560, 204800);
    transpose_w_kernel<<<(2560 * 128 + 255) / 256, 256>>>(w2, 2560, 532480);

    cin_main<<<2048 / NBATCH, BLKT>>>(x, b0, b1, b2, wl, out);
}